// round 11
// baseline (speedup 1.0000x reference)
#include <cuda_runtime.h>
#include <cuda_bf16.h>
#include <cstdint>

// ---------------- problem constants ----------------
#define IN_CH   512
#define HID     128
#define OUT_CH  128
#define MAXN    1000000
#define MAXSEG  50000
#define NT16    (IN_CH / 16)       // 32 k16-steps

// ---------------- device scratch ----------------
__device__ __align__(16) float g_h[(size_t)MAXN * HID];
__device__ float    g_a[MAXN];
__device__ float    g_e[MAXN];
__device__ unsigned g_smax[MAXSEG];
__device__ float    g_denom[MAXSEG];
__device__ __align__(16) float g_pooled[(size_t)MAXSEG * HID];
// W fragments in mma.sync B-operand register layout:
// index = ((t16 * 8) + n16blk) * 32 + lane, 16B each (regs b0,b1,b2,b3)
__device__ __align__(16) uint4 g_Wfh[NT16 * 8 * 32];
__device__ __align__(16) uint4 g_Wfl[NT16 * 8 * 32];

// ---------------- helpers ----------------
#define MMA16816(c, a0, a1, a2, a3, b0, b1) \
    asm volatile("mma.sync.aligned.m16n8k16.row.col.f32.bf16.bf16.f32 " \
                 "{%0,%1,%2,%3}, {%4,%5,%6,%7}, {%8,%9}, {%0,%1,%2,%3};" \
                 : "+f"((c)[0]), "+f"((c)[1]), "+f"((c)[2]), "+f"((c)[3]) \
                 : "r"(a0), "r"(a1), "r"(a2), "r"(a3), "r"(b0), "r"(b1))

__device__ __forceinline__ uint32_t bf2bits(__nv_bfloat162 v) {
    return *reinterpret_cast<uint32_t*>(&v);
}
// split a float2 into bf16x2 hi and bf16x2 lo (lo = residual, rounded)
__device__ __forceinline__ void split2(float2 v, uint32_t& h, uint32_t& l) {
    __nv_bfloat162 hb = __floats2bfloat162_rn(v.x, v.y);
    float2 hf = __bfloat1622float2(hb);
    __nv_bfloat162 lb = __floats2bfloat162_rn(v.x - hf.x, v.y - hf.y);
    h = bf2bits(hb);
    l = bf2bits(lb);
}
__device__ __forceinline__ uint32_t pkbf(float a, float b) {
    return bf2bits(__floats2bfloat162_rn(a, b));
}

// f32x2 helpers (k_out)
__device__ __forceinline__ unsigned long long pk(float lo, float hi) {
    unsigned long long r;
    asm("mov.b64 %0, {%1, %2};" : "=l"(r) : "f"(lo), "f"(hi));
    return r;
}
__device__ __forceinline__ void unpk(unsigned long long v, float& lo, float& hi) {
    asm("mov.b64 {%0, %1}, %2;" : "=f"(lo), "=f"(hi) : "l"(v));
}
__device__ __forceinline__ void ffma2(unsigned long long& c, unsigned long long a,
                                      unsigned long long b) {
    asm("fma.rn.f32x2 %0, %1, %2, %0;" : "+l"(c) : "l"(a), "l"(b));
}
__device__ __forceinline__ unsigned mapf(float f) {
    unsigned b = __float_as_uint(f);
    return (b & 0x80000000u) ? ~b : (b | 0x80000000u);
}
__device__ __forceinline__ float unmapf(unsigned u) {
    return (u & 0x80000000u) ? __uint_as_float(u & 0x7FFFFFFFu)
                             : __uint_as_float(~u);
}

// ---------------- kernel: build W fragment tables ----------------
__global__ void k_prepw(const float* __restrict__ W1) {
    int t = blockIdx.x * blockDim.x + threadIdx.x;
    if (t >= NT16 * 8 * 32) return;
    int lane = t & 31;
    int p    = (t >> 5) & 7;       // n16 block
    int kt   = t >> 8;             // k16 step
    int tig = lane & 3, g = lane >> 2;
    int k0 = kt * 16 + tig * 2;
    int n0 = p * 16 + g;

    float wh[8], wl[8];
#pragma unroll
    for (int r = 0; r < 4; r++) {
        int k = k0 + (r & 1) * 8;
        int n = n0 + (r >> 1) * 8;
#pragma unroll
        for (int e = 0; e < 2; e++) {
            float w = W1[(size_t)(k + e) * HID + n];
            __nv_bfloat16 hb = __float2bfloat16(w);
            float hf = __bfloat162float(hb);
            wh[r * 2 + e] = hf;
            wl[r * 2 + e] = w - hf;
        }
    }
    size_t base = ((size_t)kt * 8 + p) * 32 + lane;
    uint4 H, L;
    H.x = pkbf(wh[0], wh[1]); H.y = pkbf(wh[2], wh[3]);
    H.z = pkbf(wh[4], wh[5]); H.w = pkbf(wh[6], wh[7]);
    L.x = pkbf(wl[0], wl[1]); L.y = pkbf(wl[2], wl[3]);
    L.z = pkbf(wl[4], wl[5]); L.w = pkbf(wl[6], wl[7]);
    g_Wfh[base] = H;
    g_Wfl[base] = L;
}

// ---------------- kernel: zero scratch ----------------
__global__ void k_init(int S) {
    int t = blockIdx.x * blockDim.x + threadIdx.x;
    int stride = gridDim.x * blockDim.x;
    for (int i = t; i < S; i += stride) { g_smax[i] = 0u; g_denom[i] = 0.0f; }
    int tot = S * HID;
    for (int i = t; i < tot; i += stride) g_pooled[i] = 0.0f;
}

// ---------------- GEMM1: 8 M-warps x full-N, register fragments -------------
// CTA = 256 threads = 8 warps; warp tile 16(M) x 128(N); CTA tile 128 rows.
__global__ void __launch_bounds__(256, 2)
k_gemm1(const float* __restrict__ x, const float* __restrict__ b1,
        const float* __restrict__ Wa, const float* __restrict__ ba, int N) {
    int tid = threadIdx.x, wid = tid >> 5, lane = tid & 31;
    int tig = lane & 3, g = lane >> 2;
    long row0 = (long)blockIdx.x * 128;

    long rA = row0 + wid * 16 + g;
    long rB = rA + 8;
    bool ok0 = rA < N, ok1 = rB < N;
    const float* xp0 = x + (ok0 ? rA : 0) * (long)IN_CH;
    const float* xp1 = x + (ok1 ? rB : 0) * (long)IN_CH;

    float acc[16][4];
#pragma unroll
    for (int b = 0; b < 16; b++)
#pragma unroll
        for (int q = 0; q < 4; q++) acc[b][q] = 0.0f;

    const float2 z2 = make_float2(0.f, 0.f);
    // pipelined A registers: [row half][k half]
    float2 v00, v10, v01, v11;
    {
        int c0 = tig * 2;
        v00 = ok0 ? *(const float2*)(xp0 + c0) : z2;
        v10 = ok1 ? *(const float2*)(xp1 + c0) : z2;
        v01 = ok0 ? *(const float2*)(xp0 + c0 + 8) : z2;
        v11 = ok1 ? *(const float2*)(xp1 + c0 + 8) : z2;
    }

#pragma unroll 1
    for (int t = 0; t < NT16; ++t) {
        // ---- split current A to bf16 hi/lo fragments ----
        uint32_t ah[4], al[4];
        split2(v00, ah[0], al[0]);
        split2(v10, ah[1], al[1]);
        split2(v01, ah[2], al[2]);
        split2(v11, ah[3], al[3]);

        // ---- load A for t+1 (hide LDG latency behind MMAs) ----
        if (t + 1 < NT16) {
            int c1 = (t + 1) * 16 + tig * 2;
            v00 = ok0 ? *(const float2*)(xp0 + c1) : z2;
            v10 = ok1 ? *(const float2*)(xp1 + c1) : z2;
            v01 = ok0 ? *(const float2*)(xp0 + c1 + 8) : z2;
            v11 = ok1 ? *(const float2*)(xp1 + c1 + 8) : z2;
        }
        // L2 prefetch a few k16 ahead
        if (tig == 0 && t + 3 < NT16) {
            asm volatile("prefetch.global.L2 [%0];" :: "l"(xp0 + (t + 3) * 16));
            asm volatile("prefetch.global.L2 [%0];" :: "l"(xp1 + (t + 3) * 16));
        }

        // ---- B fragments from L1/L2-hot table, 1-ahead prefetch ----
        size_t tb = ((size_t)t * 8) * 32 + lane;
        uint4 bh = g_Wfh[tb], bl = g_Wfl[tb];
#pragma unroll
        for (int p = 0; p < 8; p++) {
            uint4 nbh, nbl;
            if (p < 7) { nbh = g_Wfh[tb + 32 * (p + 1)]; nbl = g_Wfl[tb + 32 * (p + 1)]; }
            MMA16816(acc[2 * p + 0], ah[0], ah[1], ah[2], ah[3], bh.x, bh.y);
            MMA16816(acc[2 * p + 1], ah[0], ah[1], ah[2], ah[3], bh.z, bh.w);
            MMA16816(acc[2 * p + 0], ah[0], ah[1], ah[2], ah[3], bl.x, bl.y);
            MMA16816(acc[2 * p + 1], ah[0], ah[1], ah[2], ah[3], bl.z, bl.w);
            MMA16816(acc[2 * p + 0], al[0], al[1], al[2], al[3], bh.x, bh.y);
            MMA16816(acc[2 * p + 1], al[0], al[1], al[2], al[3], bh.z, bh.w);
            bh = nbh; bl = nbl;
        }
    }

    // ---- epilogue: bias + silu + logit + store h (one warp owns a row) ----
    float ba0 = ba[0];
#pragma unroll
    for (int rh = 0; rh < 2; rh++) {
        long grow = rh ? rB : rA;
        bool okr = rh ? ok1 : ok0;
        float part = 0.0f;
        if (okr) {
            float* hrow = g_h + (size_t)grow * HID;
#pragma unroll
            for (int nt = 0; nt < 16; nt++) {
                int cb = nt * 8 + tig * 2;
                float2 bb = *(const float2*)&b1[cb];
                float2 ww = *(const float2*)&Wa[cb];
                float v0 = acc[nt][rh * 2 + 0] + bb.x;
                float v1 = acc[nt][rh * 2 + 1] + bb.y;
                float s0 = v0 / (1.0f + __expf(-v0));
                float s1 = v1 / (1.0f + __expf(-v1));
                part += s0 * ww.x + s1 * ww.y;
                *(float2*)(hrow + cb) = make_float2(s0, s1);
            }
        }
        part += __shfl_xor_sync(0xffffffffu, part, 1);
        part += __shfl_xor_sync(0xffffffffu, part, 2);
        if (tig == 0 && okr) g_a[grow] = part + ba0;
    }
}

// ---------------- kernel: segment max ----------------
#define CHUNK 16
__global__ void k_segmax(const int* __restrict__ idx, int N) {
    int t = blockIdx.x * blockDim.x + threadIdx.x;
    int start = t * CHUNK;
    if (start >= N) return;
    int end = min(start + CHUNK, N);
    int cur = idx[start];
    float mx = g_a[start];
    for (int i = start + 1; i < end; i++) {
        int s = idx[i];
        float v = g_a[i];
        if (s == cur) mx = fmaxf(mx, v);
        else { atomicMax(&g_smax[cur], mapf(mx)); cur = s; mx = v; }
    }
    atomicMax(&g_smax[cur], mapf(mx));
}

// ---------------- kernel: exp + denom ----------------
__global__ void k_exp(const int* __restrict__ idx, int N) {
    int t = blockIdx.x * blockDim.x + threadIdx.x;
    int start = t * CHUNK;
    if (start >= N) return;
    int end = min(start + CHUNK, N);
    int cur = idx[start];
    float m = unmapf(g_smax[cur]);
    float ex = __expf(g_a[start] - m);
    g_e[start] = ex;
    float sum = ex;
    for (int i = start + 1; i < end; i++) {
        int s = idx[i];
        if (s != cur) {
            atomicAdd(&g_denom[cur], sum);
            cur = s; m = unmapf(g_smax[cur]); sum = 0.0f;
        }
        float e2 = __expf(g_a[i] - m);
        g_e[i] = e2;
        sum += e2;
    }
    atomicAdd(&g_denom[cur], sum);
}

// ---------------- kernel: weighted pooling over sorted runs ----------------
__global__ void __launch_bounds__(128)
k_pool(const int* __restrict__ idx, int N) {
    __shared__ int s_idx[256];
    __shared__ float s_w[256];
    int base = blockIdx.x * 256;
    int tid = threadIdx.x;
    for (int r = tid; r < 256; r += 128) {
        int row = base + r;
        if (row < N) {
            int sg = idx[row];
            s_idx[r] = sg;
            s_w[r] = g_e[row] / g_denom[sg];
        } else {
            s_idx[r] = -1;
        }
    }
    __syncthreads();

    int j = tid;
    float sum = 0.0f;
    int cur = s_idx[0];
#pragma unroll 1
    for (int rb = 0; rb < 256; rb += 8) {
        float hv[8];
#pragma unroll
        for (int u = 0; u < 8; u++)
            hv[u] = (s_idx[rb + u] >= 0)
                        ? g_h[(size_t)(base + rb + u) * HID + j] : 0.0f;
#pragma unroll
        for (int u = 0; u < 8; u++) {
            int sg = s_idx[rb + u];
            if (sg < 0) goto done;
            if (sg != cur) {
                atomicAdd(&g_pooled[(size_t)cur * HID + j], sum);
                sum = 0.0f; cur = sg;
            }
            sum += s_w[rb + u] * hv[u];
        }
    }
done:
    atomicAdd(&g_pooled[(size_t)cur * HID + j], sum);
}

// ---------------- kernel: out = pooled @ Wo + bo ----------------
__global__ void __launch_bounds__(256)
k_out(const float* __restrict__ Wo, const float* __restrict__ bo,
      float* __restrict__ out, int S) {
    __shared__ __align__(16) float Ps[64][HID];
    int tid = threadIdx.x;
    int row0 = blockIdx.x * 64;
#pragma unroll
    for (int i = 0; i < 8; i++) {
        int id = tid + i * 256;
        int r = id >> 5, c4 = id & 31;
        float4 v = make_float4(0.f, 0.f, 0.f, 0.f);
        if (row0 + r < S)
            v = *(const float4*)&g_pooled[(size_t)(row0 + r) * HID + c4 * 4];
        *(float4*)&Ps[r][c4 * 4] = v;
    }
    __syncthreads();

    int m_base = (tid >> 5) * 8;
    int n_base = (tid & 31) * 4;
    unsigned long long acc[8][2] = {};
#pragma unroll 4
    for (int k = 0; k < HID; k++) {
        float4 b = *(const float4*)&Wo[(size_t)k * OUT_CH + n_base];
        unsigned long long b0 = pk(b.x, b.y), b1p = pk(b.z, b.w);
#pragma unroll
        for (int mi = 0; mi < 8; mi++) {
            float av = Ps[m_base + mi][k];
            unsigned long long ad = pk(av, av);
            ffma2(acc[mi][0], ad, b0);
            ffma2(acc[mi][1], ad, b1p);
        }
    }
    float c0 = bo[n_base], c1 = bo[n_base + 1], c2 = bo[n_base + 2], c3 = bo[n_base + 3];
#pragma unroll
    for (int mi = 0; mi < 8; mi++) {
        int row = row0 + m_base + mi;
        if (row < S) {
            float l0, h0, l1, h1;
            unpk(acc[mi][0], l0, h0);
            unpk(acc[mi][1], l1, h1);
            *(float4*)&out[(size_t)row * OUT_CH + n_base] =
                make_float4(l0 + c0, h0 + c1, l1 + c2, h1 + c3);
        }
    }
}

// ---------------- launch ----------------
extern "C" void kernel_launch(void* const* d_in, const int* in_sizes, int n_in,
                              void* d_out, int out_size) {
    const float* x     = (const float*)d_in[0];
    const int*   index = (const int*)d_in[1];
    const float* W1 = (const float*)d_in[n_in - 6];
    const float* b1 = (const float*)d_in[n_in - 5];
    const float* Wa = (const float*)d_in[n_in - 4];
    const float* ba = (const float*)d_in[n_in - 3];
    const float* Wo = (const float*)d_in[n_in - 2];
    const float* bo = (const float*)d_in[n_in - 1];
    float* out = (float*)d_out;

    int N = in_sizes[0] / IN_CH;       // 1,000,000
    int S = out_size / OUT_CH;         // 50,000

    k_prepw<<<(NT16 * 8 * 32 + 255) / 256, 256>>>(W1);
    k_init<<<256, 256>>>(S);
    k_gemm1<<<(N + 127) / 128, 256>>>(x, b1, Wa, ba, N);
    int ct = (N + CHUNK - 1) / CHUNK;
    k_segmax<<<(ct + 255) / 256, 256>>>(index, N);
    k_exp<<<(ct + 255) / 256, 256>>>(index, N);
    k_pool<<<(N + 255) / 256, 128>>>(index, N);
    k_out<<<(S + 63) / 64, 256>>>(Wo, bo, out, S);
}

// round 12
// speedup vs baseline: 1.0526x; 1.0526x over previous
#include <cuda_runtime.h>
#include <cuda_bf16.h>
#include <cstdint>

// ---------------- problem constants ----------------
#define IN_CH   512
#define HID     128
#define OUT_CH  128
#define MAXN    1000000
#define MAXSEG  50000
#define NT16    (IN_CH / 16)       // 32 k16-steps

// ---------------- device scratch ----------------
__device__ __align__(16) float g_h[(size_t)MAXN * HID];
__device__ float    g_a[MAXN];
__device__ float    g_e[MAXN];
__device__ unsigned g_smax[MAXSEG];
__device__ float    g_denom[MAXSEG];
__device__ __align__(16) float g_pooled[(size_t)MAXSEG * HID];
// W fragments in mma.sync B-operand register layout:
// index = ((t16 * 8) + n16blk) * 32 + lane, 16B each (regs b0,b1,b2,b3)
__device__ __align__(16) uint4 g_Wfh[NT16 * 8 * 32];
__device__ __align__(16) uint4 g_Wfl[NT16 * 8 * 32];

// ---------------- helpers ----------------
#define MMA16816(c, a0, a1, a2, a3, b0, b1) \
    asm volatile("mma.sync.aligned.m16n8k16.row.col.f32.bf16.bf16.f32 " \
                 "{%0,%1,%2,%3}, {%4,%5,%6,%7}, {%8,%9}, {%0,%1,%2,%3};" \
                 : "+f"((c)[0]), "+f"((c)[1]), "+f"((c)[2]), "+f"((c)[3]) \
                 : "r"(a0), "r"(a1), "r"(a2), "r"(a3), "r"(b0), "r"(b1))

__device__ __forceinline__ uint32_t bf2bits(__nv_bfloat162 v) {
    return *reinterpret_cast<uint32_t*>(&v);
}
// split a float2 into bf16x2 hi and bf16x2 lo (lo = residual, rounded)
__device__ __forceinline__ void split2(float2 v, uint32_t& h, uint32_t& l) {
    __nv_bfloat162 hb = __floats2bfloat162_rn(v.x, v.y);
    float2 hf = __bfloat1622float2(hb);
    __nv_bfloat162 lb = __floats2bfloat162_rn(v.x - hf.x, v.y - hf.y);
    h = bf2bits(hb);
    l = bf2bits(lb);
}
__device__ __forceinline__ uint32_t pkbf(float a, float b) {
    return bf2bits(__floats2bfloat162_rn(a, b));
}

// f32x2 helpers (k_out)
__device__ __forceinline__ unsigned long long pk(float lo, float hi) {
    unsigned long long r;
    asm("mov.b64 %0, {%1, %2};" : "=l"(r) : "f"(lo), "f"(hi));
    return r;
}
__device__ __forceinline__ void unpk(unsigned long long v, float& lo, float& hi) {
    asm("mov.b64 {%0, %1}, %2;" : "=f"(lo), "=f"(hi) : "l"(v));
}
__device__ __forceinline__ void ffma2(unsigned long long& c, unsigned long long a,
                                      unsigned long long b) {
    asm("fma.rn.f32x2 %0, %1, %2, %0;" : "+l"(c) : "l"(a), "l"(b));
}
__device__ __forceinline__ unsigned mapf(float f) {
    unsigned b = __float_as_uint(f);
    return (b & 0x80000000u) ? ~b : (b | 0x80000000u);
}
__device__ __forceinline__ float unmapf(unsigned u) {
    return (u & 0x80000000u) ? __uint_as_float(u & 0x7FFFFFFFu)
                             : __uint_as_float(~u);
}

// ---------------- kernel: build W fragment tables ----------------
__global__ void k_prepw(const float* __restrict__ W1) {
    int t = blockIdx.x * blockDim.x + threadIdx.x;
    if (t >= NT16 * 8 * 32) return;
    int lane = t & 31;
    int p    = (t >> 5) & 7;       // n16 block
    int kt   = t >> 8;             // k16 step
    int tig = lane & 3, g = lane >> 2;
    int k0 = kt * 16 + tig * 2;
    int n0 = p * 16 + g;

    float wh[8], wl[8];
#pragma unroll
    for (int r = 0; r < 4; r++) {
        int k = k0 + (r & 1) * 8;
        int n = n0 + (r >> 1) * 8;
#pragma unroll
        for (int e = 0; e < 2; e++) {
            float w = W1[(size_t)(k + e) * HID + n];
            __nv_bfloat16 hb = __float2bfloat16(w);
            float hf = __bfloat162float(hb);
            wh[r * 2 + e] = hf;
            wl[r * 2 + e] = w - hf;
        }
    }
    size_t base = ((size_t)kt * 8 + p) * 32 + lane;
    uint4 H, L;
    H.x = pkbf(wh[0], wh[1]); H.y = pkbf(wh[2], wh[3]);
    H.z = pkbf(wh[4], wh[5]); H.w = pkbf(wh[6], wh[7]);
    L.x = pkbf(wl[0], wl[1]); L.y = pkbf(wl[2], wl[3]);
    L.z = pkbf(wl[4], wl[5]); L.w = pkbf(wl[6], wl[7]);
    g_Wfh[base] = H;
    g_Wfl[base] = L;
}

// ---------------- kernel: zero scratch ----------------
__global__ void k_init(int S) {
    int t = blockIdx.x * blockDim.x + threadIdx.x;
    int stride = gridDim.x * blockDim.x;
    for (int i = t; i < S; i += stride) { g_smax[i] = 0u; g_denom[i] = 0.0f; }
    int tot4 = (S * HID) >> 2;
    float4* p4 = (float4*)g_pooled;
    float4 z = make_float4(0.f, 0.f, 0.f, 0.f);
    for (int i = t; i < tot4; i += stride) p4[i] = z;
}

// ---------------- GEMM1: 4(M)x2(N) warps, register fragments, pipelined A ---
// CTA = 256 threads = 8 warps; warp tile 32(M) x 64(N); CTA tile 128 rows.
__global__ void __launch_bounds__(256, 2)
k_gemm1(const float* __restrict__ x, const float* __restrict__ b1,
        const float* __restrict__ Wa, const float* __restrict__ ba, int N) {
    __shared__ float s_a[128];
    int tid = threadIdx.x, wid = tid >> 5, lane = tid & 31;
    int mw = wid & 3, nw = wid >> 2;
    int tig = lane & 3, g = lane >> 2;
    long row0 = (long)blockIdx.x * 128;

    if (tid < 128) s_a[tid] = 0.0f;
    __syncthreads();

    // per-lane A row pointers: rows row0 + mw*32 + mt*16 + rr*8 + g
    const float* xp[2][2];
    bool ok[2][2];
#pragma unroll
    for (int mt = 0; mt < 2; mt++)
#pragma unroll
        for (int rr = 0; rr < 2; rr++) {
            long r = row0 + mw * 32 + mt * 16 + rr * 8 + g;
            ok[mt][rr] = r < N;
            xp[mt][rr] = x + (ok[mt][rr] ? r : 0) * (long)IN_CH;
        }

    float acc[2][8][4];
#pragma unroll
    for (int a = 0; a < 2; a++)
#pragma unroll
        for (int b = 0; b < 8; b++)
#pragma unroll
            for (int q = 0; q < 4; q++) acc[a][b][q] = 0.0f;

    int bbase = nw * 4;   // first n16 block for this warp
    const float2 z2 = make_float2(0.f, 0.f);

    // ---- preload + split t = 0 ----
    uint32_t ah[2][4], al[2][4];
    {
        int c0 = tig * 2;
#pragma unroll
        for (int mt = 0; mt < 2; mt++) {
            float2 a0 = ok[mt][0] ? *(const float2*)(xp[mt][0] + c0) : z2;
            float2 a1 = ok[mt][1] ? *(const float2*)(xp[mt][1] + c0) : z2;
            float2 a2 = ok[mt][0] ? *(const float2*)(xp[mt][0] + c0 + 8) : z2;
            float2 a3 = ok[mt][1] ? *(const float2*)(xp[mt][1] + c0 + 8) : z2;
            split2(a0, ah[mt][0], al[mt][0]);
            split2(a1, ah[mt][1], al[mt][1]);
            split2(a2, ah[mt][2], al[mt][2]);
            split2(a3, ah[mt][3], al[mt][3]);
        }
    }

#pragma unroll 1
    for (int t = 0; t < NT16; ++t) {
        // ---- issue A loads for t+1 FIRST (latency hidden by 48 MMAs) ----
        float2 v[2][4];
        if (t + 1 < NT16) {
            int c1 = (t + 1) * 16 + tig * 2;
#pragma unroll
            for (int mt = 0; mt < 2; mt++) {
                v[mt][0] = ok[mt][0] ? *(const float2*)(xp[mt][0] + c1) : z2;
                v[mt][1] = ok[mt][1] ? *(const float2*)(xp[mt][1] + c1) : z2;
                v[mt][2] = ok[mt][0] ? *(const float2*)(xp[mt][0] + c1 + 8) : z2;
                v[mt][3] = ok[mt][1] ? *(const float2*)(xp[mt][1] + c1 + 8) : z2;
            }
        }
        // L2 prefetch the DRAM side a few k16 ahead
        if (tig == 0 && t + 3 < NT16) {
#pragma unroll
            for (int mt = 0; mt < 2; mt++)
#pragma unroll
                for (int rr = 0; rr < 2; rr++)
                    if (ok[mt][rr])
                        asm volatile("prefetch.global.L2 [%0];"
                                     :: "l"(xp[mt][rr] + (t + 3) * 16));
        }

        // ---- B fragments via LDG (L1/L2-hot table), 1-ahead; 12-MMA p-steps
        size_t tb = ((size_t)t * 8 + bbase) * 32 + lane;
        uint4 bh = g_Wfh[tb], bl = g_Wfl[tb];
#pragma unroll
        for (int pp = 0; pp < 4; pp++) {
            uint4 nbh, nbl;
            if (pp < 3) { nbh = g_Wfh[tb + 32 * (pp + 1)]; nbl = g_Wfl[tb + 32 * (pp + 1)]; }
#pragma unroll
            for (int mt = 0; mt < 2; mt++) {
                MMA16816(acc[mt][2 * pp + 0], ah[mt][0], ah[mt][1], ah[mt][2], ah[mt][3], bh.x, bh.y);
                MMA16816(acc[mt][2 * pp + 1], ah[mt][0], ah[mt][1], ah[mt][2], ah[mt][3], bh.z, bh.w);
                MMA16816(acc[mt][2 * pp + 0], ah[mt][0], ah[mt][1], ah[mt][2], ah[mt][3], bl.x, bl.y);
                MMA16816(acc[mt][2 * pp + 1], ah[mt][0], ah[mt][1], ah[mt][2], ah[mt][3], bl.z, bl.w);
                MMA16816(acc[mt][2 * pp + 0], al[mt][0], al[mt][1], al[mt][2], al[mt][3], bh.x, bh.y);
                MMA16816(acc[mt][2 * pp + 1], al[mt][0], al[mt][1], al[mt][2], al[mt][3], bh.z, bh.w);
            }
            bh = nbh; bl = nbl;
        }

        // ---- split t+1 A (data has arrived behind the MMA wall) ----
        if (t + 1 < NT16) {
#pragma unroll
            for (int mt = 0; mt < 2; mt++) {
                split2(v[mt][0], ah[mt][0], al[mt][0]);
                split2(v[mt][1], ah[mt][1], al[mt][1]);
                split2(v[mt][2], ah[mt][2], al[mt][2]);
                split2(v[mt][3], ah[mt][3], al[mt][3]);
            }
        }
    }

    // ---- epilogue: bias + silu + logit + store h ----
    float2 b1v[8], wav[8];
#pragma unroll
    for (int nt = 0; nt < 8; nt++) {
        int cb = nw * 64 + nt * 8 + tig * 2;
        b1v[nt] = *(const float2*)&b1[cb];
        wav[nt] = *(const float2*)&Wa[cb];
    }
    long r0g = row0 + mw * 32 + g;
#pragma unroll
    for (int mt = 0; mt < 2; mt++) {
#pragma unroll
        for (int rh = 0; rh < 2; rh++) {
            long grow = r0g + mt * 16 + rh * 8;
            float part = 0.0f;
            if (grow < N) {
                float* hrow = g_h + (size_t)grow * HID;
#pragma unroll
                for (int nt = 0; nt < 8; nt++) {
                    float v0 = acc[mt][nt][rh * 2 + 0] + b1v[nt].x;
                    float v1 = acc[mt][nt][rh * 2 + 1] + b1v[nt].y;
                    float s0 = v0 / (1.0f + __expf(-v0));
                    float s1 = v1 / (1.0f + __expf(-v1));
                    part += s0 * wav[nt].x + s1 * wav[nt].y;
                    int cb = nw * 64 + nt * 8 + tig * 2;
                    *(float2*)(hrow + cb) = make_float2(s0, s1);
                }
            }
            part += __shfl_xor_sync(0xffffffffu, part, 1);
            part += __shfl_xor_sync(0xffffffffu, part, 2);
            if (tig == 0 && grow < N)
                atomicAdd(&s_a[(int)(grow - row0)], part);
        }
    }
    __syncthreads();
    if (tid < 128) {
        long row = row0 + tid;
        if (row < N) g_a[row] = s_a[tid] + ba[0];
    }
}

// ---------------- kernel: segment max ----------------
#define CHUNK 16
__global__ void k_segmax(const int* __restrict__ idx, int N) {
    int t = blockIdx.x * blockDim.x + threadIdx.x;
    int start = t * CHUNK;
    if (start >= N) return;
    int end = min(start + CHUNK, N);
    int cur = idx[start];
    float mx = g_a[start];
    for (int i = start + 1; i < end; i++) {
        int s = idx[i];
        float v = g_a[i];
        if (s == cur) mx = fmaxf(mx, v);
        else { atomicMax(&g_smax[cur], mapf(mx)); cur = s; mx = v; }
    }
    atomicMax(&g_smax[cur], mapf(mx));
}

// ---------------- kernel: exp + denom ----------------
__global__ void k_exp(const int* __restrict__ idx, int N) {
    int t = blockIdx.x * blockDim.x + threadIdx.x;
    int start = t * CHUNK;
    if (start >= N) return;
    int end = min(start + CHUNK, N);
    int cur = idx[start];
    float m = unmapf(g_smax[cur]);
    float ex = __expf(g_a[start] - m);
    g_e[start] = ex;
    float sum = ex;
    for (int i = start + 1; i < end; i++) {
        int s = idx[i];
        if (s != cur) {
            atomicAdd(&g_denom[cur], sum);
            cur = s; m = unmapf(g_smax[cur]); sum = 0.0f;
        }
        float e2 = __expf(g_a[i] - m);
        g_e[i] = e2;
        sum += e2;
    }
    atomicAdd(&g_denom[cur], sum);
}

// ---------------- kernel: weighted pooling over sorted runs ----------------
__global__ void __launch_bounds__(128)
k_pool(const int* __restrict__ idx, int N) {
    __shared__ int s_idx[256];
    __shared__ float s_w[256];
    int base = blockIdx.x * 256;
    int tid = threadIdx.x;
    for (int r = tid; r < 256; r += 128) {
        int row = base + r;
        if (row < N) {
            int sg = idx[row];
            s_idx[r] = sg;
            s_w[r] = g_e[row] / g_denom[sg];
        } else {
            s_idx[r] = -1;
        }
    }
    __syncthreads();

    int j = tid;
    float sum = 0.0f;
    int cur = s_idx[0];
#pragma unroll 1
    for (int rb = 0; rb < 256; rb += 8) {
        float hv[8];
#pragma unroll
        for (int u = 0; u < 8; u++)
            hv[u] = (s_idx[rb + u] >= 0)
                        ? g_h[(size_t)(base + rb + u) * HID + j] : 0.0f;
#pragma unroll
        for (int u = 0; u < 8; u++) {
            int sg = s_idx[rb + u];
            if (sg < 0) goto done;
            if (sg != cur) {
                atomicAdd(&g_pooled[(size_t)cur * HID + j], sum);
                sum = 0.0f; cur = sg;
            }
            sum += s_w[rb + u] * hv[u];
        }
    }
done:
    atomicAdd(&g_pooled[(size_t)cur * HID + j], sum);
}

// ---------------- kernel: out = pooled @ Wo + bo ----------------
__global__ void __launch_bounds__(256)
k_out(const float* __restrict__ Wo, const float* __restrict__ bo,
      float* __restrict__ out, int S) {
    __shared__ __align__(16) float Ps[64][HID];
    int tid = threadIdx.x;
    int row0 = blockIdx.x * 64;
#pragma unroll
    for (int i = 0; i < 8; i++) {
        int id = tid + i * 256;
        int r = id >> 5, c4 = id & 31;
        float4 v = make_float4(0.f, 0.f, 0.f, 0.f);
        if (row0 + r < S)
            v = *(const float4*)&g_pooled[(size_t)(row0 + r) * HID + c4 * 4];
        *(float4*)&Ps[r][c4 * 4] = v;
    }
    __syncthreads();

    int m_base = (tid >> 5) * 8;
    int n_base = (tid & 31) * 4;
    unsigned long long acc[8][2] = {};
#pragma unroll 4
    for (int k = 0; k < HID; k++) {
        float4 b = *(const float4*)&Wo[(size_t)k * OUT_CH + n_base];
        unsigned long long b0 = pk(b.x, b.y), b1p = pk(b.z, b.w);
#pragma unroll
        for (int mi = 0; mi < 8; mi++) {
            float av = Ps[m_base + mi][k];
            unsigned long long ad = pk(av, av);
            ffma2(acc[mi][0], ad, b0);
            ffma2(acc[mi][1], ad, b1p);
        }
    }
    float c0 = bo[n_base], c1 = bo[n_base + 1], c2 = bo[n_base + 2], c3 = bo[n_base + 3];
#pragma unroll
    for (int mi = 0; mi < 8; mi++) {
        int row = row0 + m_base + mi;
        if (row < S) {
            float l0, h0, l1, h1;
            unpk(acc[mi][0], l0, h0);
            unpk(acc[mi][1], l1, h1);
            *(float4*)&out[(size_t)row * OUT_CH + n_base] =
                make_float4(l0 + c0, h0 + c1, l1 + c2, h1 + c3);
        }
    }
}

// ---------------- launch ----------------
extern "C" void kernel_launch(void* const* d_in, const int* in_sizes, int n_in,
                              void* d_out, int out_size) {
    const float* x     = (const float*)d_in[0];
    const int*   index = (const int*)d_in[1];
    const float* W1 = (const float*)d_in[n_in - 6];
    const float* b1 = (const float*)d_in[n_in - 5];
    const float* Wa = (const float*)d_in[n_in - 4];
    const float* ba = (const float*)d_in[n_in - 3];
    const float* Wo = (const float*)d_in[n_in - 2];
    const float* bo = (const float*)d_in[n_in - 1];
    float* out = (float*)d_out;

    int N = in_sizes[0] / IN_CH;       // 1,000,000
    int S = out_size / OUT_CH;         // 50,000

    k_prepw<<<(NT16 * 8 * 32 + 255) / 256, 256>>>(W1);
    k_init<<<256, 256>>>(S);
    k_gemm1<<<(N + 127) / 128, 256>>>(x, b1, Wa, ba, N);
    int ct = (N + CHUNK - 1) / CHUNK;
    k_segmax<<<(ct + 255) / 256, 256>>>(index, N);
    k_exp<<<(ct + 255) / 256, 256>>>(index, N);
    k_pool<<<(N + 255) / 256, 128>>>(index, N);
    k_out<<<(S + 63) / 64, 256>>>(Wo, bo, out, S);
}

// round 13
// speedup vs baseline: 1.2189x; 1.1580x over previous
#include <cuda_runtime.h>
#include <cuda_bf16.h>
#include <cstdint>

// ---------------- problem constants ----------------
#define IN_CH   512
#define HID     128
#define OUT_CH  128
#define MAXN    1000000
#define MAXSEG  50000
#define NT16    (IN_CH / 16)       // 32 k16-steps

// ---------------- device scratch ----------------
__device__ __align__(16) float g_h[(size_t)MAXN * HID];
__device__ float    g_a[MAXN];
__device__ float    g_e[MAXN];
__device__ unsigned g_smax[MAXSEG];
__device__ float    g_denom[MAXSEG];
__device__ __align__(16) float g_pooled[(size_t)MAXSEG * HID];
// W fragments in mma.sync B-operand register layout:
// index = ((t16 * 8) + n16blk) * 32 + lane, 16B each (regs b0,b1,b2,b3)
__device__ __align__(16) uint4 g_Wfh[NT16 * 8 * 32];
__device__ __align__(16) uint4 g_Wfl[NT16 * 8 * 32];

// ---------------- helpers ----------------
#define MMA16816(c, a0, a1, a2, a3, b0, b1) \
    asm volatile("mma.sync.aligned.m16n8k16.row.col.f32.bf16.bf16.f32 " \
                 "{%0,%1,%2,%3}, {%4,%5,%6,%7}, {%8,%9}, {%0,%1,%2,%3};" \
                 : "+f"((c)[0]), "+f"((c)[1]), "+f"((c)[2]), "+f"((c)[3]) \
                 : "r"(a0), "r"(a1), "r"(a2), "r"(a3), "r"(b0), "r"(b1))

__device__ __forceinline__ uint32_t bf2bits(__nv_bfloat162 v) {
    return *reinterpret_cast<uint32_t*>(&v);
}
// split a float2 into bf16x2 hi and bf16x2 lo (lo = residual, rounded)
__device__ __forceinline__ void split2(float2 v, uint32_t& h, uint32_t& l) {
    __nv_bfloat162 hb = __floats2bfloat162_rn(v.x, v.y);
    float2 hf = __bfloat1622float2(hb);
    __nv_bfloat162 lb = __floats2bfloat162_rn(v.x - hf.x, v.y - hf.y);
    h = bf2bits(hb);
    l = bf2bits(lb);
}
__device__ __forceinline__ uint32_t pkbf(float a, float b) {
    return bf2bits(__floats2bfloat162_rn(a, b));
}

// f32x2 helpers (k_out)
__device__ __forceinline__ unsigned long long pk(float lo, float hi) {
    unsigned long long r;
    asm("mov.b64 %0, {%1, %2};" : "=l"(r) : "f"(lo), "f"(hi));
    return r;
}
__device__ __forceinline__ void unpk(unsigned long long v, float& lo, float& hi) {
    asm("mov.b64 {%0, %1}, %2;" : "=f"(lo), "=f"(hi) : "l"(v));
}
__device__ __forceinline__ void ffma2(unsigned long long& c, unsigned long long a,
                                      unsigned long long b) {
    asm("fma.rn.f32x2 %0, %1, %2, %0;" : "+l"(c) : "l"(a), "l"(b));
}
__device__ __forceinline__ unsigned mapf(float f) {
    unsigned b = __float_as_uint(f);
    return (b & 0x80000000u) ? ~b : (b | 0x80000000u);
}
__device__ __forceinline__ float unmapf(unsigned u) {
    return (u & 0x80000000u) ? __uint_as_float(u & 0x7FFFFFFFu)
                             : __uint_as_float(~u);
}

// ---------------- kernel: build W fragment tables ----------------
__global__ void k_prepw(const float* __restrict__ W1) {
    int t = blockIdx.x * blockDim.x + threadIdx.x;
    if (t >= NT16 * 8 * 32) return;
    int lane = t & 31;
    int p    = (t >> 5) & 7;       // n16 block
    int kt   = t >> 8;             // k16 step
    int tig = lane & 3, g = lane >> 2;
    int k0 = kt * 16 + tig * 2;
    int n0 = p * 16 + g;

    float wh[8], wl[8];
#pragma unroll
    for (int r = 0; r < 4; r++) {
        int k = k0 + (r & 1) * 8;
        int n = n0 + (r >> 1) * 8;
#pragma unroll
        for (int e = 0; e < 2; e++) {
            float w = W1[(size_t)(k + e) * HID + n];
            __nv_bfloat16 hb = __float2bfloat16(w);
            float hf = __bfloat162float(hb);
            wh[r * 2 + e] = hf;
            wl[r * 2 + e] = w - hf;
        }
    }
    size_t base = ((size_t)kt * 8 + p) * 32 + lane;
    uint4 H, L;
    H.x = pkbf(wh[0], wh[1]); H.y = pkbf(wh[2], wh[3]);
    H.z = pkbf(wh[4], wh[5]); H.w = pkbf(wh[6], wh[7]);
    L.x = pkbf(wl[0], wl[1]); L.y = pkbf(wl[2], wl[3]);
    L.z = pkbf(wl[4], wl[5]); L.w = pkbf(wl[6], wl[7]);
    g_Wfh[base] = H;
    g_Wfl[base] = L;
}

// ---------------- kernels: zero scratch (split so gemm1 lands in the
// ncu-profiled launch slot #4) ----------------
__global__ void k_init_seg(int S) {
    int t = blockIdx.x * blockDim.x + threadIdx.x;
    int stride = gridDim.x * blockDim.x;
    for (int i = t; i < S; i += stride) { g_smax[i] = 0u; g_denom[i] = 0.0f; }
}
__global__ void k_init_pool(int S) {
    int t = blockIdx.x * blockDim.x + threadIdx.x;
    int stride = gridDim.x * blockDim.x;
    int tot4 = (S * HID) >> 2;
    float4* p4 = (float4*)g_pooled;
    float4 z = make_float4(0.f, 0.f, 0.f, 0.f);
    for (int i = t; i < tot4; i += stride) p4[i] = z;
}

// ---------------- GEMM1: 4(M)x2(N) warps, register fragments (R10) ----------
// CTA = 256 threads = 8 warps; warp tile 32(M) x 64(N); CTA tile 128 rows.
__global__ void __launch_bounds__(256, 2)
k_gemm1(const float* __restrict__ x, const float* __restrict__ b1,
        const float* __restrict__ Wa, const float* __restrict__ ba, int N) {
    __shared__ float s_a[128];
    int tid = threadIdx.x, wid = tid >> 5, lane = tid & 31;
    int mw = wid & 3, nw = wid >> 2;
    int tig = lane & 3, g = lane >> 2;
    long row0 = (long)blockIdx.x * 128;

    if (tid < 128) s_a[tid] = 0.0f;
    __syncthreads();

    // per-lane A row pointers: rows row0 + mw*32 + mt*16 + rr*8 + g
    const float* xp[2][2];
    bool ok[2][2];
#pragma unroll
    for (int mt = 0; mt < 2; mt++)
#pragma unroll
        for (int rr = 0; rr < 2; rr++) {
            long r = row0 + mw * 32 + mt * 16 + rr * 8 + g;
            ok[mt][rr] = r < N;
            xp[mt][rr] = x + (ok[mt][rr] ? r : 0) * (long)IN_CH;
        }

    float acc[2][8][4];
#pragma unroll
    for (int a = 0; a < 2; a++)
#pragma unroll
        for (int b = 0; b < 8; b++)
#pragma unroll
            for (int q = 0; q < 4; q++) acc[a][b][q] = 0.0f;

    int bbase = nw * 4;   // first n16 block for this warp

#pragma unroll 1
    for (int t = 0; t < NT16; ++t) {
        int c0 = t * 16 + tig * 2;
        // ---- A loads (fp32, exactly the fragment elements) ----
        float2 v[2][2][2];
#pragma unroll
        for (int mt = 0; mt < 2; mt++)
#pragma unroll
            for (int rr = 0; rr < 2; rr++) {
                v[mt][rr][0] = ok[mt][rr] ? *(const float2*)(xp[mt][rr] + c0)
                                          : make_float2(0.f, 0.f);
                v[mt][rr][1] = ok[mt][rr] ? *(const float2*)(xp[mt][rr] + c0 + 8)
                                          : make_float2(0.f, 0.f);
            }
        // L2 prefetch next-next k16 line of x
        if (tig == 0 && t + 2 < NT16) {
#pragma unroll
            for (int mt = 0; mt < 2; mt++)
#pragma unroll
                for (int rr = 0; rr < 2; rr++)
                    if (ok[mt][rr])
                        asm volatile("prefetch.global.L2 [%0];"
                                     :: "l"(xp[mt][rr] + (t + 2) * 16));
        }
        // ---- split to bf16 hi/lo fragments in registers ----
        uint32_t ah[2][4], al[2][4];
#pragma unroll
        for (int mt = 0; mt < 2; mt++) {
            split2(v[mt][0][0], ah[mt][0], al[mt][0]);
            split2(v[mt][1][0], ah[mt][1], al[mt][1]);
            split2(v[mt][0][1], ah[mt][2], al[mt][2]);
            split2(v[mt][1][1], ah[mt][3], al[mt][3]);
        }
        // ---- B fragments via LDG (L2-hot table), JIT with 1-ahead ----
        size_t tb = ((size_t)t * 8 + bbase) * 32 + lane;
        uint4 bh = g_Wfh[tb], bl = g_Wfl[tb];
#pragma unroll
        for (int pp = 0; pp < 4; pp++) {
            uint4 nbh, nbl;
            if (pp < 3) { nbh = g_Wfh[tb + 32 * (pp + 1)]; nbl = g_Wfl[tb + 32 * (pp + 1)]; }
#pragma unroll
            for (int mt = 0; mt < 2; mt++) {
                MMA16816(acc[mt][2 * pp + 0], ah[mt][0], ah[mt][1], ah[mt][2], ah[mt][3], bh.x, bh.y);
                MMA16816(acc[mt][2 * pp + 1], ah[mt][0], ah[mt][1], ah[mt][2], ah[mt][3], bh.z, bh.w);
                MMA16816(acc[mt][2 * pp + 0], ah[mt][0], ah[mt][1], ah[mt][2], ah[mt][3], bl.x, bl.y);
                MMA16816(acc[mt][2 * pp + 1], ah[mt][0], ah[mt][1], ah[mt][2], ah[mt][3], bl.z, bl.w);
                MMA16816(acc[mt][2 * pp + 0], al[mt][0], al[mt][1], al[mt][2], al[mt][3], bh.x, bh.y);
                MMA16816(acc[mt][2 * pp + 1], al[mt][0], al[mt][1], al[mt][2], al[mt][3], bh.z, bh.w);
            }
            bh = nbh; bl = nbl;
        }
    }

    // ---- epilogue: bias + silu + logit + store h ----
    float2 b1v[8], wav[8];
#pragma unroll
    for (int nt = 0; nt < 8; nt++) {
        int cb = nw * 64 + nt * 8 + tig * 2;
        b1v[nt] = *(const float2*)&b1[cb];
        wav[nt] = *(const float2*)&Wa[cb];
    }
    long r0g = row0 + mw * 32 + g;
#pragma unroll
    for (int mt = 0; mt < 2; mt++) {
#pragma unroll
        for (int rh = 0; rh < 2; rh++) {
            long grow = r0g + mt * 16 + rh * 8;
            float part = 0.0f;
            if (grow < N) {
                float* hrow = g_h + (size_t)grow * HID;
#pragma unroll
                for (int nt = 0; nt < 8; nt++) {
                    float v0 = acc[mt][nt][rh * 2 + 0] + b1v[nt].x;
                    float v1 = acc[mt][nt][rh * 2 + 1] + b1v[nt].y;
                    float s0 = v0 / (1.0f + __expf(-v0));
                    float s1 = v1 / (1.0f + __expf(-v1));
                    part += s0 * wav[nt].x + s1 * wav[nt].y;
                    int cb = nw * 64 + nt * 8 + tig * 2;
                    *(float2*)(hrow + cb) = make_float2(s0, s1);
                }
            }
            part += __shfl_xor_sync(0xffffffffu, part, 1);
            part += __shfl_xor_sync(0xffffffffu, part, 2);
            if (tig == 0 && grow < N)
                atomicAdd(&s_a[(int)(grow - row0)], part);
        }
    }
    __syncthreads();
    if (tid < 128) {
        long row = row0 + tid;
        if (row < N) g_a[row] = s_a[tid] + ba[0];
    }
}

// ---------------- kernel: segment max ----------------
#define CHUNK 16
__global__ void k_segmax(const int* __restrict__ idx, int N) {
    int t = blockIdx.x * blockDim.x + threadIdx.x;
    int start = t * CHUNK;
    if (start >= N) return;
    int end = min(start + CHUNK, N);
    int cur = idx[start];
    float mx = g_a[start];
    for (int i = start + 1; i < end; i++) {
        int s = idx[i];
        float v = g_a[i];
        if (s == cur) mx = fmaxf(mx, v);
        else { atomicMax(&g_smax[cur], mapf(mx)); cur = s; mx = v; }
    }
    atomicMax(&g_smax[cur], mapf(mx));
}

// ---------------- kernel: exp + denom ----------------
__global__ void k_exp(const int* __restrict__ idx, int N) {
    int t = blockIdx.x * blockDim.x + threadIdx.x;
    int start = t * CHUNK;
    if (start >= N) return;
    int end = min(start + CHUNK, N);
    int cur = idx[start];
    float m = unmapf(g_smax[cur]);
    float ex = __expf(g_a[start] - m);
    g_e[start] = ex;
    float sum = ex;
    for (int i = start + 1; i < end; i++) {
        int s = idx[i];
        if (s != cur) {
            atomicAdd(&g_denom[cur], sum);
            cur = s; m = unmapf(g_smax[cur]); sum = 0.0f;
        }
        float e2 = __expf(g_a[i] - m);
        g_e[i] = e2;
        sum += e2;
    }
    atomicAdd(&g_denom[cur], sum);
}

// ---------------- kernel: weighted pooling over sorted runs ----------------
__global__ void __launch_bounds__(128)
k_pool(const int* __restrict__ idx, int N) {
    __shared__ int s_idx[256];
    __shared__ float s_w[256];
    int base = blockIdx.x * 256;
    int tid = threadIdx.x;
    for (int r = tid; r < 256; r += 128) {
        int row = base + r;
        if (row < N) {
            int sg = idx[row];
            s_idx[r] = sg;
            s_w[r] = g_e[row] / g_denom[sg];
        } else {
            s_idx[r] = -1;
        }
    }
    __syncthreads();

    int j = tid;
    float sum = 0.0f;
    int cur = s_idx[0];
#pragma unroll 1
    for (int rb = 0; rb < 256; rb += 8) {
        float hv[8];
#pragma unroll
        for (int u = 0; u < 8; u++)
            hv[u] = (s_idx[rb + u] >= 0)
                        ? g_h[(size_t)(base + rb + u) * HID + j] : 0.0f;
#pragma unroll
        for (int u = 0; u < 8; u++) {
            int sg = s_idx[rb + u];
            if (sg < 0) goto done;
            if (sg != cur) {
                atomicAdd(&g_pooled[(size_t)cur * HID + j], sum);
                sum = 0.0f; cur = sg;
            }
            sum += s_w[rb + u] * hv[u];
        }
    }
done:
    atomicAdd(&g_pooled[(size_t)cur * HID + j], sum);
}

// ---------------- kernel: out = pooled @ Wo + bo ----------------
__global__ void __launch_bounds__(256)
k_out(const float* __restrict__ Wo, const float* __restrict__ bo,
      float* __restrict__ out, int S) {
    __shared__ __align__(16) float Ps[64][HID];
    int tid = threadIdx.x;
    int row0 = blockIdx.x * 64;
#pragma unroll
    for (int i = 0; i < 8; i++) {
        int id = tid + i * 256;
        int r = id >> 5, c4 = id & 31;
        float4 v = make_float4(0.f, 0.f, 0.f, 0.f);
        if (row0 + r < S)
            v = *(const float4*)&g_pooled[(size_t)(row0 + r) * HID + c4 * 4];
        *(float4*)&Ps[r][c4 * 4] = v;
    }
    __syncthreads();

    int m_base = (tid >> 5) * 8;
    int n_base = (tid & 31) * 4;
    unsigned long long acc[8][2] = {};
#pragma unroll 4
    for (int k = 0; k < HID; k++) {
        float4 b = *(const float4*)&Wo[(size_t)k * OUT_CH + n_base];
        unsigned long long b0 = pk(b.x, b.y), b1p = pk(b.z, b.w);
#pragma unroll
        for (int mi = 0; mi < 8; mi++) {
            float av = Ps[m_base + mi][k];
            unsigned long long ad = pk(av, av);
            ffma2(acc[mi][0], ad, b0);
            ffma2(acc[mi][1], ad, b1p);
        }
    }
    float c0 = bo[n_base], c1 = bo[n_base + 1], c2 = bo[n_base + 2], c3 = bo[n_base + 3];
#pragma unroll
    for (int mi = 0; mi < 8; mi++) {
        int row = row0 + m_base + mi;
        if (row < S) {
            float l0, h0, l1, h1;
            unpk(acc[mi][0], l0, h0);
            unpk(acc[mi][1], l1, h1);
            *(float4*)&out[(size_t)row * OUT_CH + n_base] =
                make_float4(l0 + c0, h0 + c1, l1 + c2, h1 + c3);
        }
    }
}

// ---------------- launch ----------------
extern "C" void kernel_launch(void* const* d_in, const int* in_sizes, int n_in,
                              void* d_out, int out_size) {
    const float* x     = (const float*)d_in[0];
    const int*   index = (const int*)d_in[1];
    const float* W1 = (const float*)d_in[n_in - 6];
    const float* b1 = (const float*)d_in[n_in - 5];
    const float* Wa = (const float*)d_in[n_in - 4];
    const float* ba = (const float*)d_in[n_in - 3];
    const float* Wo = (const float*)d_in[n_in - 2];
    const float* bo = (const float*)d_in[n_in - 1];
    float* out = (float*)d_out;

    int N = in_sizes[0] / IN_CH;       // 1,000,000
    int S = out_size / OUT_CH;         // 50,000

    // launch order: gemm1 must be the 4th launch (ncu-profiled slot)
    k_prepw<<<(NT16 * 8 * 32 + 255) / 256, 256>>>(W1);       // 1
    k_init_seg<<<64, 256>>>(S);                              // 2
    k_init_pool<<<256, 256>>>(S);                            // 3
    k_gemm1<<<(N + 127) / 128, 256>>>(x, b1, Wa, ba, N);     // 4  <- profiled
    int ct = (N + CHUNK - 1) / CHUNK;
    k_segmax<<<(ct + 255) / 256, 256>>>(index, N);           // 5
    k_exp<<<(ct + 255) / 256, 256>>>(index, N);              // 6
    k_pool<<<(N + 255) / 256, 128>>>(index, N);              // 7
    k_out<<<(S + 63) / 64, 256>>>(Wo, bo, out, S);           // 8
}